// round 7
// baseline (speedup 1.0000x reference)
#include <cuda_runtime.h>
#include <cstdint>

// Problem constants (fixed-shape problem)
#define B_  4
#define S_  2048
#define D_  1024
#define H_  16
#define DH_ 64
#define M_  (B_ * S_)   // 8192 rows for all projections

typedef unsigned long long ull;

// ---------------------------------------------------------------------------
// Packed f32x2 helpers (SASS FFMA2 — 2 fp32 FMAs per instruction, rt_SMSP=2)
// ---------------------------------------------------------------------------
__device__ __forceinline__ ull pack2(float lo, float hi) {
    ull r;
    asm("mov.b64 %0, {%1, %2};" : "=l"(r) : "f"(lo), "f"(hi));
    return r;
}
__device__ __forceinline__ void unpack2(ull v, float& lo, float& hi) {
    asm("mov.b64 {%0, %1}, %2;" : "=f"(lo), "=f"(hi) : "l"(v));
}
__device__ __forceinline__ ull fma2(ull a, ull b, ull c) {
    ull d;
    asm("fma.rn.f32x2 %0, %1, %2, %3;" : "=l"(d) : "l"(a), "l"(b), "l"(c));
    return d;
}

// ---------------------------------------------------------------------------
// Scratch (device globals: allocation-free, graph-capturable)
// q,k,v in [B,H,S,Dh]; o_concat in [B,S,D]
// ---------------------------------------------------------------------------
__device__ float g_q[B_ * H_ * S_ * DH_];
__device__ float g_k[B_ * H_ * S_ * DH_];
__device__ float g_v[B_ * H_ * S_ * DH_];
__device__ float g_o[B_ * S_ * D_];

// ---------------------------------------------------------------------------
// GEMM (NT): C[M,N] = A[M,K] * W[N,K]^T + bias[N]
// MODE 0: C row-major [M,N]
// MODE 1: scatter to [B,H,S,Dh]  (row = b*S+s, col = h*64+dh)
// 128x128 block, BK=8, 256 threads, 8x8 microtile, packed f32x2 math.
// B-operand lane pairs (j, j+1) are contiguous in smem -> loaded directly as
// ulonglong2 (no packing); A-operand broadcast-packed (8 packs / k-step).
// ---------------------------------------------------------------------------
template <int MODE>
__global__ __launch_bounds__(256) void gemm_nt(
    const float* __restrict__ A, const float* __restrict__ W,
    const float* __restrict__ bias, float* __restrict__ C,
    int M, int N, int K)
{
    __shared__ __align__(16) float As[8][128];  // transposed: As[k][m]
    __shared__ __align__(16) float Ws[8][128];  // transposed: Ws[k][n]

    const int tid = threadIdx.x;
    const int tx = tid & 15;       // 0..15
    const int ty = tid >> 4;       // 0..15
    const int bm = blockIdx.y * 128;
    const int bn = blockIdx.x * 128;

    const int lr = tid >> 1;            // 0..127 (row within tile)
    const int lc = (tid & 1) * 4;       // 0 or 4 (k offset within BK)
    const float* Ap = A + (size_t)(bm + lr) * K + lc;
    const float* Wp = W + (size_t)(bn + lr) * K + lc;

    ull acc[8][4];
#pragma unroll
    for (int i = 0; i < 8; i++)
#pragma unroll
        for (int jj = 0; jj < 4; jj++) acc[i][jj] = 0ULL;

    float4 av = *(const float4*)Ap;
    float4 wv = *(const float4*)Wp;

    for (int k0 = 0; k0 < K; k0 += 8) {
        As[lc + 0][lr] = av.x; As[lc + 1][lr] = av.y;
        As[lc + 2][lr] = av.z; As[lc + 3][lr] = av.w;
        Ws[lc + 0][lr] = wv.x; Ws[lc + 1][lr] = wv.y;
        Ws[lc + 2][lr] = wv.z; Ws[lc + 3][lr] = wv.w;
        __syncthreads();

        if (k0 + 8 < K) {
            av = *(const float4*)(Ap + k0 + 8);
            wv = *(const float4*)(Wp + k0 + 8);
        }

#pragma unroll
        for (int k = 0; k < 8; k++) {
            float a[8];
            *(float4*)(a)     = *(const float4*)&As[k][ty * 8];
            *(float4*)(a + 4) = *(const float4*)&As[k][ty * 8 + 4];
            const ulonglong2 b01 = *(const ulonglong2*)&Ws[k][tx * 8];
            const ulonglong2 b23 = *(const ulonglong2*)&Ws[k][tx * 8 + 4];
            ull b2[4];
            b2[0] = b01.x; b2[1] = b01.y; b2[2] = b23.x; b2[3] = b23.y;
#pragma unroll
            for (int i = 0; i < 8; i++) {
                const ull a2 = pack2(a[i], a[i]);
#pragma unroll
                for (int jj = 0; jj < 4; jj++)
                    acc[i][jj] = fma2(a2, b2[jj], acc[i][jj]);
            }
        }
        __syncthreads();
    }

    // epilogue
#pragma unroll
    for (int i = 0; i < 8; i++) {
        const int row = bm + ty * 8 + i;
#pragma unroll
        for (int jj = 0; jj < 4; jj++) {
            float v0, v1;
            unpack2(acc[i][jj], v0, v1);
            const int col0 = bn + tx * 8 + 2 * jj;
            const float r0 = v0 + bias[col0];
            const float r1 = v1 + bias[col0 + 1];
            if (MODE == 0) {
                C[(size_t)row * N + col0]     = r0;
                C[(size_t)row * N + col0 + 1] = r1;
            } else {
                const int bb = row >> 11;          // row / S_
                const int ss = row & (S_ - 1);
                const int h  = col0 >> 6;          // col / DH_ (pair never crosses a head: col0 even)
                const int dh = col0 & (DH_ - 1);
                float* dst = &((float*)0)[0];      // silence unused warn pattern
                (void)dst;
                float* base = (float*)C + (((size_t)(bb * H_ + h)) * S_ + ss) * DH_ + dh;
                base[0] = r0;
                base[1] = r1;
            }
        }
    }
}

// ---------------------------------------------------------------------------
// Sigmoid attention, per (b,h): O = sigmoid(Q K^T / 8) V    (packed f32x2)
// Q tile 128 rows; KV tile 128 rows; Dh = 64; 256 threads.
// Stage 1: rows ty+16i (lanes = i-pairs), cols tx+16j.
// Stage 2: rows ty+16i (lanes = i-pairs), cols tx*4+j (contiguous dh -> V via
//          one LDS.128, coalesced float4 output stores).
// Pads: Qs/Ks stride 65, Vs stride 64, Ps stride 129 (bank-conflict-free).
// ---------------------------------------------------------------------------
__global__ __launch_bounds__(256) void attn_kernel(
    const float* __restrict__ Qg, const float* __restrict__ Kg,
    const float* __restrict__ Vg, float* __restrict__ Og)
{
    extern __shared__ float sm[];
    float* Qs = sm;                    // [128][65]
    float* Ks = Qs + 128 * 65;         // [128][65]
    float* Vs = Ks + 128 * 65;         // [128][64]
    float* Ps = Vs + 128 * 64;         // [128][129]

    const int tid = threadIdx.x;
    const int tx = tid & 15;
    const int ty = tid >> 4;
    const int bh = blockIdx.y;             // 0..63  (b*H + h)
    const int q0 = blockIdx.x * 128;

    const float* Qp = Qg + (size_t)bh * S_ * DH_;
    const float* Kp = Kg + (size_t)bh * S_ * DH_;
    const float* Vp = Vg + (size_t)bh * S_ * DH_;

    // load Q tile [128,64] once (padded stride 65)
#pragma unroll
    for (int it = 0; it < 8; it++) {
        const int f = tid + it * 256;
        const int r = f >> 4;
        const int c = (f & 15) << 2;
        const float4 qv = *(const float4*)(Qp + (size_t)(q0 + r) * DH_ + c);
        float* qd = &Qs[r * 65 + c];
        qd[0] = qv.x; qd[1] = qv.y; qd[2] = qv.z; qd[3] = qv.w;
    }

    ull o2[4][4];   // lanes = i-pair (rows ty+16*(2ii), ty+16*(2ii+1)); cols tx*4+j
#pragma unroll
    for (int ii = 0; ii < 4; ii++)
#pragma unroll
        for (int j = 0; j < 4; j++) o2[ii][j] = 0ULL;

    for (int j0 = 0; j0 < S_; j0 += 128) {
        __syncthreads();  // prev iter's Ps/Vs reads complete before overwrite

        // load K (stride 65) and V (stride 64) tiles
#pragma unroll
        for (int it = 0; it < 8; it++) {
            const int f = tid + it * 256;
            const int r = f >> 4;
            const int c = (f & 15) << 2;
            const float4 kv = *(const float4*)(Kp + (size_t)(j0 + r) * DH_ + c);
            float* kd = &Ks[r * 65 + c];
            kd[0] = kv.x; kd[1] = kv.y; kd[2] = kv.z; kd[3] = kv.w;
            *(float4*)&Vs[r * 64 + c] =
                *(const float4*)(Vp + (size_t)(j0 + r) * DH_ + c);
        }
        __syncthreads();

        // Stage 1: S[128q x 128kv] = Q * K^T, lanes over i-pairs
        ull s2[4][8];
#pragma unroll
        for (int ii = 0; ii < 4; ii++)
#pragma unroll
            for (int j = 0; j < 8; j++) s2[ii][j] = 0ULL;

#pragma unroll 8
        for (int k = 0; k < DH_; k++) {
            float a[8], b[8];
#pragma unroll
            for (int i = 0; i < 8; i++) a[i] = Qs[(ty + 16 * i) * 65 + k];
#pragma unroll
            for (int j = 0; j < 8; j++) b[j] = Ks[(tx + 16 * j) * 65 + k];
            ull a2[4];
#pragma unroll
            for (int ii = 0; ii < 4; ii++) a2[ii] = pack2(a[2 * ii], a[2 * ii + 1]);
#pragma unroll
            for (int j = 0; j < 8; j++) {
                const ull b2 = pack2(b[j], b[j]);
#pragma unroll
                for (int ii = 0; ii < 4; ii++)
                    s2[ii][j] = fma2(a2[ii], b2, s2[ii][j]);
            }
        }

        // sigmoid(s/8) -> Ps (stride 129)
#pragma unroll
        for (int ii = 0; ii < 4; ii++) {
            const int r0 = (ty + 16 * (2 * ii)) * 129;
            const int r1 = (ty + 16 * (2 * ii + 1)) * 129;
#pragma unroll
            for (int j = 0; j < 8; j++) {
                float x0, x1;
                unpack2(s2[ii][j], x0, x1);
                const int col = tx + 16 * j;
                Ps[r0 + col] = __fdividef(1.0f, 1.0f + __expf(-x0 * 0.125f));
                Ps[r1 + col] = __fdividef(1.0f, 1.0f + __expf(-x1 * 0.125f));
            }
        }
        __syncthreads();

        // Stage 2: O[128q x 64dh] += P * V, lanes over i-pairs, cols tx*4+j
#pragma unroll 8
        for (int k = 0; k < 128; k++) {
            float p[8];
#pragma unroll
            for (int i = 0; i < 8; i++) p[i] = Ps[(ty + 16 * i) * 129 + k];
            ull p2[4];
#pragma unroll
            for (int ii = 0; ii < 4; ii++) p2[ii] = pack2(p[2 * ii], p[2 * ii + 1]);
            const float4 vvv = *(const float4*)&Vs[k * 64 + tx * 4];
            const float vv[4] = {vvv.x, vvv.y, vvv.z, vvv.w};
#pragma unroll
            for (int j = 0; j < 4; j++) {
                const ull v2 = pack2(vv[j], vv[j]);
#pragma unroll
                for (int ii = 0; ii < 4; ii++)
                    o2[ii][j] = fma2(p2[ii], v2, o2[ii][j]);
            }
        }
    }

    // write O to concat layout [B,S,D]: o_concat[b][s][h*64 + tx*4 + j]
    const int bb = bh >> 4;
    const int h  = bh & (H_ - 1);
#pragma unroll
    for (int ii = 0; ii < 4; ii++) {
        float lo[4], hi[4];
#pragma unroll
        for (int j = 0; j < 4; j++) unpack2(o2[ii][j], lo[j], hi[j]);
        const int s0 = q0 + ty + 16 * (2 * ii);
        const int s1 = q0 + ty + 16 * (2 * ii + 1);
        float4 w0 = make_float4(lo[0], lo[1], lo[2], lo[3]);
        float4 w1 = make_float4(hi[0], hi[1], hi[2], hi[3]);
        *(float4*)&Og[((size_t)bb * S_ + s0) * D_ + h * DH_ + tx * 4] = w0;
        *(float4*)&Og[((size_t)bb * S_ + s1) * D_ + h * DH_ + tx * 4] = w1;
    }
}

// ---------------------------------------------------------------------------
// Launcher
// ---------------------------------------------------------------------------
extern "C" void kernel_launch(void* const* d_in, const int* in_sizes, int n_in,
                              void* d_out, int out_size)
{
    const float* q  = (const float*)d_in[0];
    const float* k  = (const float*)d_in[1];
    const float* v  = (const float*)d_in[2];
    const float* Wq = (const float*)d_in[3];
    const float* bq = (const float*)d_in[4];
    const float* Wk = (const float*)d_in[5];
    const float* bk = (const float*)d_in[6];
    const float* Wv = (const float*)d_in[7];
    const float* bv = (const float*)d_in[8];
    const float* Wo = (const float*)d_in[9];
    const float* bo = (const float*)d_in[10];
    float* out = (float*)d_out;

    float *gq, *gk, *gv, *go;
    cudaGetSymbolAddress((void**)&gq, g_q);
    cudaGetSymbolAddress((void**)&gk, g_k);
    cudaGetSymbolAddress((void**)&gv, g_v);
    cudaGetSymbolAddress((void**)&go, g_o);

    const dim3 gg(D_ / 128, M_ / 128);  // (8, 64)

    gemm_nt<1><<<gg, 256>>>(q, Wq, bq, gq, M_, D_, D_);
    gemm_nt<1><<<gg, 256>>>(k, Wk, bk, gk, M_, D_, D_);
    gemm_nt<1><<<gg, 256>>>(v, Wv, bv, gv, M_, D_, D_);

    const int attn_smem =
        (128 * 65 + 128 * 65 + 128 * 64 + 128 * 129) * (int)sizeof(float);
    cudaFuncSetAttribute(attn_kernel, cudaFuncAttributeMaxDynamicSharedMemorySize, attn_smem);
    attn_kernel<<<dim3(S_ / 128, B_ * H_), 256, attn_smem>>>(gq, gk, gv, go);

    gemm_nt<0><<<gg, 256>>>(go, Wo, bo, out, M_, D_, D_);
}